// round 2
// baseline (speedup 1.0000x reference)
#include <cuda_runtime.h>
#include <cuda_bf16.h>
#include <math.h>

// Problem constants (fixed bench shapes)
#define BH    32            // B*H = 4*8
#define LSEQ  2048          // sequence length
#define DIM   64            // head dim
#define USEL  40            // u = U_part = 5*ceil(ln(2048)) = 40
#define NCH   8             // key chunks for split-softmax attention
#define CHK   (LSEQ/NCH)    // 256 keys per chunk

// -------- scratch (device globals; no allocation allowed) --------
__device__ float g_M[BH * LSEQ];                    // sparsity scores
__device__ int   g_topk[BH * USEL];                 // selected query indices
__device__ float g_meanV[BH * DIM];                 // per-(b,h) mean of V
__device__ float g_pm[BH * NCH * USEL];             // partial softmax max
__device__ float g_pl[BH * NCH * USEL];             // partial softmax denom
__device__ float g_pacc[(size_t)BH * NCH * USEL * DIM]; // partial outputs (2.6 MB)

// ================= 1. mean of V per (b,h) =================
__global__ void mean_kernel(const float* __restrict__ V) {
    __shared__ float sb[256];
    int bh = blockIdx.x, t = threadIdx.x;
    int d = t & 63, part = t >> 6;
    const float* Vb = V + (size_t)bh * LSEQ * DIM;
    float s = 0.f;
    for (int l = part; l < LSEQ; l += 4)
        s += Vb[(size_t)l * DIM + d];
    sb[t] = s;
    __syncthreads();
    if (t < 64)
        g_meanV[bh * DIM + t] =
            (sb[t] + sb[t + 64] + sb[t + 128] + sb[t + 192]) * (1.0f / LSEQ);
}

// ================= 2. broadcast-fill output with meanV =================
__global__ void fill_kernel(float4* __restrict__ out) {
    int i = blockIdx.x * blockDim.x + threadIdx.x;   // over BH*LSEQ*16 float4s
    int bh = i >> 15;                                // LSEQ*16 = 32768
    int d4 = i & 15;
    out[i] = ((const float4*)g_meanV)[bh * 16 + d4];
}

// ================= 3. M scores (sampled QK gather) =================
// one warp per (bh, q). Warp stages its Q row in smem (broadcast reads);
// each LANE computes a full 64-dim dot for one sample (16x LDG.128, MLP=16).
// Round 1: lanes 0..31 take samples 0..31. Round 2: lanes < u-32 take the rest.
// Then ONE warp reduction for (max, sum) over all u samples.
__global__ __launch_bounds__(256) void m_kernel(const float* __restrict__ Q,
                                                const float* __restrict__ K,
                                                const int* __restrict__ idxs, int u) {
    __shared__ float Qs[8][64];
    int w = threadIdx.x >> 5, lane = threadIdx.x & 31;
    int gw = blockIdx.x * 8 + w;
    int bh = gw >> 11;                 // /LSEQ
    int q  = gw & (LSEQ - 1);

    const float* Qr = Q + ((size_t)bh * LSEQ + q) * DIM;
    Qs[w][lane]      = Qr[lane];
    Qs[w][lane + 32] = Qr[lane + 32];
    __syncwarp();

    const int* ip = idxs + (size_t)q * u;
    const float* Kb = K + (size_t)bh * LSEQ * DIM;
    const float4* Qv = (const float4*)Qs[w];

    // round 1: sample = lane
    int k1 = __ldg(ip + lane);
    const float4* K1 = (const float4*)(Kb + (size_t)k1 * DIM);
    float d1 = 0.f;
#pragma unroll
    for (int c = 0; c < 16; c++) {
        float4 kv = __ldg(K1 + c);
        float4 qv = Qv[c];
        d1 = fmaf(kv.x, qv.x, d1);
        d1 = fmaf(kv.y, qv.y, d1);
        d1 = fmaf(kv.z, qv.z, d1);
        d1 = fmaf(kv.w, qv.w, d1);
    }

    // round 2: sample = 32 + lane (only lanes < u-32 active)
    float d2max = -1e30f, d2sum = 0.f;
    if (lane < u - 32) {
        int k2 = __ldg(ip + 32 + lane);
        const float4* K2 = (const float4*)(Kb + (size_t)k2 * DIM);
        float a = 0.f;
#pragma unroll
        for (int c = 0; c < 16; c++) {
            float4 kv = __ldg(K2 + c);
            float4 qv = Qv[c];
            a = fmaf(kv.x, qv.x, a);
            a = fmaf(kv.y, qv.y, a);
            a = fmaf(kv.z, qv.z, a);
            a = fmaf(kv.w, qv.w, a);
        }
        d2max = a; d2sum = a;
    }

    float m = fmaxf(d1, d2max);
    float s = d1 + d2sum;
#pragma unroll
    for (int o = 16; o; o >>= 1) {
        m = fmaxf(m, __shfl_xor_sync(0xFFFFFFFFu, m, o));
        s += __shfl_xor_sync(0xFFFFFFFFu, s, o);
    }
    if (lane == 0)
        g_M[bh * LSEQ + q] = m - s * (1.0f / LSEQ);
}

// ================= 4. top-40 per (b,h) via radix select =================
// Monotone float->uint key map; 4x 8-bit histogram passes find the exact key
// of the 40th-largest value, then one compaction pass emits the index set.
// Ties at the threshold resolved to smallest indices (matches jax top_k set).
__device__ __forceinline__ unsigned f2key(float x) {
    unsigned k = __float_as_uint(x);
    return (k & 0x80000000u) ? ~k : (k | 0x80000000u);
}

__global__ __launch_bounds__(256) void topk_kernel() {
    __shared__ unsigned skeys[LSEQ];        // 8 KB
    __shared__ unsigned hist[256];
    __shared__ int ebuf[64];
    __shared__ unsigned s_prefix;
    __shared__ int s_remaining, s_cnt, s_eq;

    int bh = blockIdx.x, t = threadIdx.x;
    for (int i = t; i < LSEQ; i += 256)
        skeys[i] = f2key(g_M[bh * LSEQ + i]);
    if (t == 0) { s_prefix = 0u; s_remaining = USEL; s_cnt = 0; s_eq = 0; }
    __syncthreads();

    const unsigned himask[4] = {0u, 0xFF000000u, 0xFFFF0000u, 0xFFFFFF00u};
#pragma unroll
    for (int r = 0; r < 4; r++) {
        int shift = 24 - 8 * r;
        hist[t] = 0;                         // blockDim == 256
        __syncthreads();
        unsigned pfx = s_prefix;
        for (int i = t; i < LSEQ; i += 256) {
            unsigned k = skeys[i];
            if ((k & himask[r]) == pfx)
                atomicAdd(&hist[(k >> shift) & 255u], 1u);
        }
        __syncthreads();
        if (t == 0) {
            int rem = s_remaining;
            unsigned cum = 0;
            for (int b = 255; b >= 0; b--) {
                unsigned c = hist[b];
                cum += c;
                if ((int)cum >= rem) {
                    s_prefix = pfx | ((unsigned)b << shift);
                    s_remaining = rem - (int)(cum - c);
                    break;
                }
            }
        }
        __syncthreads();
    }

    unsigned T = s_prefix;          // exact key of the 40th-largest value
    int need_eq = s_remaining;      // how many == T to take

    // compaction: strictly greater first
    for (int i = t; i < LSEQ; i += 256) {
        unsigned k = skeys[i];
        if (k > T) {
            int p = atomicAdd(&s_cnt, 1);
            g_topk[bh * USEL + p] = i;
        } else if (k == T) {
            int p = atomicAdd(&s_eq, 1);
            if (p < 64) ebuf[p] = i;
        }
    }
    __syncthreads();

    int cnt_gt = s_cnt, cnt_eq = s_eq;
    if (cnt_eq == need_eq) {
        // take all equals (order in g_topk irrelevant downstream)
        if (t < cnt_eq)
            g_topk[bh * USEL + cnt_gt + t] = ebuf[t];
    } else if (t == 0) {
        if (cnt_eq <= 64) {
            // rare: true ties across the boundary -> take smallest indices
            for (int n = 0; n < need_eq; n++) {
                int bi = -1, bv = LSEQ;
                for (int j = 0; j < cnt_eq; j++)
                    if (ebuf[j] < bv) { bv = ebuf[j]; bi = j; }
                g_topk[bh * USEL + cnt_gt + n] = bv;
                ebuf[bi] = LSEQ;     // mark taken
            }
        } else {
            // degenerate: >64 exact ties; serial ascending scan
            int n = 0;
            for (int i = 0; i < LSEQ && n < need_eq; i++)
                if (skeys[i] == T) g_topk[bh * USEL + cnt_gt + n++] = i;
        }
    }
}

// ================= 5. attention partials: block = (key-chunk, bh) =================
__global__ __launch_bounds__(256) void attn_kernel(const float* __restrict__ Q,
                                                   const float* __restrict__ K,
                                                   const float* __restrict__ V) {
    __shared__ float Qs[USEL * DIM];     // 10.0 KB (pre-scaled Q)
    __shared__ float KV[64 * 65];        // 16.25 KB (K tile, then V tile)
    __shared__ float Pt[USEL * 64];      // 10.0 KB (scores -> probs)
    __shared__ float s_m[USEL], s_l[USEL], s_f[USEL], s_tm[USEL];

    int ch = blockIdx.x, bh = blockIdx.y;
    int t = threadIdx.x;
    int i = t >> 5, j = t & 31;

    const float* Kb = K + (size_t)bh * LSEQ * DIM;
    const float* Vb = V + (size_t)bh * LSEQ * DIM;

    for (int e = t; e < USEL * DIM; e += 256) {
        int q = e >> 6, d = e & 63;
        int qi = g_topk[bh * USEL + q];
        Qs[e] = Q[((size_t)bh * LSEQ + qi) * DIM + d] * 0.125f;
    }
    if (t < USEL) { s_m[t] = -1e30f; s_l[t] = 0.f; }
    float acc[5][2];
#pragma unroll
    for (int a = 0; a < 5; a++) { acc[a][0] = 0.f; acc[a][1] = 0.f; }
    __syncthreads();

    int kbase0 = ch * CHK;
    for (int kt = 0; kt < CHK / 64; kt++) {
        int kb = kbase0 + kt * 64;

        for (int e = t; e < 64 * 64; e += 256) {
            int r = e >> 6, c = e & 63;
            KV[r * 65 + c] = Kb[(size_t)(kb + r) * DIM + c];
        }
        __syncthreads();

        float s[5][2];
#pragma unroll
        for (int a = 0; a < 5; a++) { s[a][0] = 0.f; s[a][1] = 0.f; }
        for (int d = 0; d < 64; d++) {
            float k0 = KV[j * 65 + d];
            float k1 = KV[(j + 32) * 65 + d];
#pragma unroll
            for (int a = 0; a < 5; a++) {
                float qv = Qs[(i + 8 * a) * 64 + d];
                s[a][0] = fmaf(qv, k0, s[a][0]);
                s[a][1] = fmaf(qv, k1, s[a][1]);
            }
        }
#pragma unroll
        for (int a = 0; a < 5; a++) {
            Pt[(i + 8 * a) * 64 + j]      = s[a][0];
            Pt[(i + 8 * a) * 64 + j + 32] = s[a][1];
        }
        __syncthreads();

        if (t < USEL) {
            float tm = -1e30f;
            for (int k = 0; k < 64; k++) tm = fmaxf(tm, Pt[t * 64 + k]);
            float mo = s_m[t];
            float mn = fmaxf(mo, tm);
            s_tm[t] = mn;
            s_f[t]  = __expf(mo - mn);
            s_m[t]  = mn;
        }
        for (int e = t; e < 64 * 64; e += 256) {
            int r = e >> 6, c = e & 63;
            KV[r * 65 + c] = Vb[(size_t)(kb + r) * DIM + c];
        }
        __syncthreads();

        for (int e = t; e < USEL * 64; e += 256) {
            int q = e >> 6;
            Pt[e] = __expf(Pt[e] - s_tm[q]);
        }
#pragma unroll
        for (int a = 0; a < 5; a++) {
            float f = s_f[i + 8 * a];
            acc[a][0] *= f;
            acc[a][1] *= f;
        }
        __syncthreads();

        if (t < USEL) {
            float su = 0.f;
            for (int k = 0; k < 64; k++) su += Pt[t * 64 + k];
            s_l[t] = s_l[t] * s_f[t] + su;
        }

        for (int k = 0; k < 64; k++) {
            float v0 = KV[k * 65 + j];
            float v1 = KV[k * 65 + j + 32];
#pragma unroll
            for (int a = 0; a < 5; a++) {
                float p = Pt[(i + 8 * a) * 64 + k];
                acc[a][0] = fmaf(p, v0, acc[a][0]);
                acc[a][1] = fmaf(p, v1, acc[a][1]);
            }
        }
        __syncthreads();
    }

    float* pa = g_pacc + (size_t)(bh * NCH + ch) * USEL * DIM;
#pragma unroll
    for (int a = 0; a < 5; a++) {
        int q = i + 8 * a;
        pa[q * DIM + j]      = acc[a][0];
        pa[q * DIM + j + 32] = acc[a][1];
    }
    if (t < USEL) {
        g_pm[(bh * NCH + ch) * USEL + t] = s_m[t];
        g_pl[(bh * NCH + ch) * USEL + t] = s_l[t];
    }
}

// ================= 6. merge partials, scatter into output =================
__global__ void merge_kernel(float* __restrict__ out) {
    int u = blockIdx.x, bh = blockIdx.y, d = threadIdx.x;
    float M = -1e30f;
#pragma unroll
    for (int c = 0; c < NCH; c++)
        M = fmaxf(M, g_pm[(bh * NCH + c) * USEL + u]);
    float L = 0.f, o = 0.f;
#pragma unroll
    for (int c = 0; c < NCH; c++) {
        float w = __expf(g_pm[(bh * NCH + c) * USEL + u] - M);
        L += g_pl[(bh * NCH + c) * USEL + u] * w;
        o = fmaf(g_pacc[((size_t)(bh * NCH + c) * USEL + u) * DIM + d], w, o);
    }
    int qi = g_topk[bh * USEL + u];
    out[((size_t)bh * LSEQ + qi) * DIM + d] = o / L;
}

// ================= launcher =================
extern "C" void kernel_launch(void* const* d_in, const int* in_sizes, int n_in,
                              void* d_out, int out_size) {
    const float* Q    = (const float*)d_in[0];
    const float* K    = (const float*)d_in[1];
    const float* V    = (const float*)d_in[2];
    const int*   idxs = (const int*)d_in[3];
    float* out = (float*)d_out;
    int u = in_sizes[3] / LSEQ;   // 40

    mean_kernel<<<BH, 256>>>(V);
    fill_kernel<<<(BH * LSEQ * 16) / 256, 256>>>((float4*)out);
    m_kernel<<<BH * LSEQ / 8, 256>>>(Q, K, idxs, u);
    topk_kernel<<<BH, 256>>>();
    attn_kernel<<<dim3(NCH, BH), 256>>>(Q, K, V);
    merge_kernel<<<dim3(USEL, BH), 64>>>(out);
}

// round 3
// speedup vs baseline: 1.9476x; 1.9476x over previous
#include <cuda_runtime.h>
#include <cuda_bf16.h>
#include <math.h>

// Problem constants (fixed bench shapes)
#define BH    32            // B*H = 4*8
#define LSEQ  2048          // sequence length
#define DIM   64            // head dim
#define USEL  40            // u = U_part = 5*ceil(ln(2048)) = 40
#define NCH   8             // key chunks for split-softmax attention
#define CHK   (LSEQ/NCH)    // 256 keys per chunk
#define KVS   68            // KV smem row stride (16B aligned, phase-conflict-free)

// -------- scratch (device globals; no allocation allowed) --------
__device__ unsigned g_Mkey[BH * LSEQ];              // monotone-mapped sparsity keys
__device__ int   g_topk[BH * USEL];                 // selected query indices
__device__ float g_meanV[BH * DIM];                 // per-(b,h) mean of V
__device__ float g_pm[BH * NCH * USEL];             // partial softmax max
__device__ float g_pl[BH * NCH * USEL];             // partial softmax denom
__device__ float g_pacc[(size_t)BH * NCH * USEL * DIM]; // partial outputs (2.6 MB)

__device__ __forceinline__ unsigned f2key(float x) {
    unsigned k = __float_as_uint(x);
    return (k & 0x80000000u) ? ~k : (k | 0x80000000u);
}

// ================= 1. mean of V per (b,h) =================
__global__ void mean_kernel(const float* __restrict__ V) {
    __shared__ float sb[256];
    int bh = blockIdx.x, t = threadIdx.x;
    int d = t & 63, part = t >> 6;
    const float* Vb = V + (size_t)bh * LSEQ * DIM;
    float s = 0.f;
    for (int l = part; l < LSEQ; l += 4)
        s += Vb[(size_t)l * DIM + d];
    sb[t] = s;
    __syncthreads();
    if (t < 64)
        g_meanV[bh * DIM + t] =
            (sb[t] + sb[t + 64] + sb[t + 128] + sb[t + 192]) * (1.0f / LSEQ);
}

// ================= 2. broadcast-fill output with meanV =================
__global__ void fill_kernel(float4* __restrict__ out) {
    int i = blockIdx.x * blockDim.x + threadIdx.x;   // over BH*LSEQ*16 float4s
    int bh = i >> 15;                                // LSEQ*16 = 32768
    int d4 = i & 15;
    out[i] = ((const float4*)g_meanV)[bh * 16 + d4];
}

// ================= 3. M scores (sampled QK gather) =================
// One warp per (bh, q). 4 samples in flight: group g (8 lanes) computes the
// dot for sample s0+g; each lane reads a CONTIGUOUS 32B chunk of the key row
// (2x LDG.128 -> 1 L2 line per group per LDG). 3-shuffle butterfly reduces
// within the group; group results folded by a 2-step butterfly at the end.
__global__ __launch_bounds__(256) void m_kernel(const float* __restrict__ Q,
                                                const float* __restrict__ K,
                                                const int* __restrict__ idxs, int u) {
    int t = threadIdx.x, lane = t & 31;
    int gw = blockIdx.x * 8 + (t >> 5);
    int bh = gw >> 11;                 // /LSEQ
    int q  = gw & (LSEQ - 1);
    int g = lane >> 3;                 // sample group 0..3
    int h = lane & 7;                  // lane within group

    const float* Qr = Q + ((size_t)bh * LSEQ + q) * DIM;
    float4 qa = __ldg((const float4*)(Qr + 8 * h));
    float4 qb = __ldg((const float4*)(Qr + 8 * h + 4));

    const int* ip = idxs + (size_t)q * u;
    int r0 = __ldg(ip + min(lane, u - 1));
    int r1 = (u > 32) ? __ldg(ip + min(32 + lane, u - 1)) : 0;

    const float* Kb = K + (size_t)bh * LSEQ * DIM;
    float mx = -1e30f, sm = 0.f;

    for (int s0 = 0; s0 < u; s0 += 4) {
        int s = s0 + g;
        int ki = (s < 32) ? __shfl_sync(0xFFFFFFFFu, r0, s)
                          : __shfl_sync(0xFFFFFFFFu, r1, s - 32);
        const float4* Kr = (const float4*)(Kb + (size_t)ki * DIM + 8 * h);
        float4 ka = __ldg(Kr);
        float4 kb4 = __ldg(Kr + 1);
        float d;
        d = qa.x * ka.x;
        d = fmaf(qa.y, ka.y, d);
        d = fmaf(qa.z, ka.z, d);
        d = fmaf(qa.w, ka.w, d);
        d = fmaf(qb.x, kb4.x, d);
        d = fmaf(qb.y, kb4.y, d);
        d = fmaf(qb.z, kb4.z, d);
        d = fmaf(qb.w, kb4.w, d);
        d += __shfl_xor_sync(0xFFFFFFFFu, d, 1);
        d += __shfl_xor_sync(0xFFFFFFFFu, d, 2);
        d += __shfl_xor_sync(0xFFFFFFFFu, d, 4);
        if (s < u) { mx = fmaxf(mx, d); sm += d; }
    }
    // fold the 4 groups
    mx = fmaxf(mx, __shfl_xor_sync(0xFFFFFFFFu, mx, 8));
    mx = fmaxf(mx, __shfl_xor_sync(0xFFFFFFFFu, mx, 16));
    sm += __shfl_xor_sync(0xFFFFFFFFu, sm, 8);
    sm += __shfl_xor_sync(0xFFFFFFFFu, sm, 16);
    if (lane == 0)
        g_Mkey[bh * LSEQ + q] = f2key(mx - sm * (1.0f / LSEQ));
}

// ================= 4. top-40 per (b,h) via radix select =================
// 4x 8-bit histogram passes with PARALLEL suffix scan, then compaction.
__global__ __launch_bounds__(256) void topk_kernel() {
    __shared__ unsigned skeys[LSEQ];        // 8 KB
    __shared__ unsigned hist[256];
    __shared__ unsigned sfx[256];
    __shared__ int ebuf[64];
    __shared__ unsigned s_prefix;
    __shared__ int s_remaining, s_cnt, s_eq;

    int bh = blockIdx.x, t = threadIdx.x;
    for (int i = t; i < LSEQ; i += 256)
        skeys[i] = g_Mkey[bh * LSEQ + i];
    if (t == 0) { s_prefix = 0u; s_remaining = USEL; s_cnt = 0; s_eq = 0; }
    __syncthreads();

    const unsigned himask[4] = {0u, 0xFF000000u, 0xFFFF0000u, 0xFFFFFF00u};
#pragma unroll
    for (int r = 0; r < 4; r++) {
        int shift = 24 - 8 * r;
        hist[t] = 0;
        __syncthreads();
        unsigned pfx = s_prefix;
        int rem = s_remaining;
        for (int i = t; i < LSEQ; i += 256) {
            unsigned k = skeys[i];
            if ((k & himask[r]) == pfx)
                atomicAdd(&hist[(k >> shift) & 255u], 1u);
        }
        __syncthreads();
        // inclusive suffix sum (Hillis-Steele)
        sfx[t] = hist[t];
        __syncthreads();
#pragma unroll
        for (int off = 1; off < 256; off <<= 1) {
            unsigned add = (t + off < 256) ? sfx[t + off] : 0u;
            __syncthreads();
            sfx[t] += add;
            __syncthreads();
        }
        unsigned S = sfx[t];
        unsigned Snext = (t < 255) ? sfx[t + 1] : 0u;
        if ((int)S >= rem && (int)Snext < rem) {
            s_prefix = pfx | ((unsigned)t << shift);
            s_remaining = rem - (int)Snext;
        }
        __syncthreads();
    }

    unsigned T = s_prefix;          // exact key of the 40th-largest value
    int need_eq = s_remaining;      // how many == T to take

    for (int i = t; i < LSEQ; i += 256) {
        unsigned k = skeys[i];
        if (k > T) {
            int p = atomicAdd(&s_cnt, 1);
            g_topk[bh * USEL + p] = i;
        } else if (k == T) {
            int p = atomicAdd(&s_eq, 1);
            if (p < 64) ebuf[p] = i;
        }
    }
    __syncthreads();

    int cnt_gt = s_cnt, cnt_eq = s_eq;
    if (cnt_eq == need_eq) {
        if (t < cnt_eq)
            g_topk[bh * USEL + cnt_gt + t] = ebuf[t];
    } else if (t == 0) {
        if (cnt_eq <= 64) {
            for (int n = 0; n < need_eq; n++) {
                int bi = -1, bv = LSEQ;
                for (int j = 0; j < cnt_eq; j++)
                    if (ebuf[j] < bv) { bv = ebuf[j]; bi = j; }
                g_topk[bh * USEL + cnt_gt + n] = bv;
                ebuf[bi] = LSEQ;
            }
        } else {
            int n = 0;
            for (int i = 0; i < LSEQ && n < need_eq; i++)
                if (skeys[i] == T) g_topk[bh * USEL + cnt_gt + n++] = i;
        }
    }
}

// ================= 5. attention partials: block = (key-chunk, bh) =================
// 256 threads: warp w owns query rows {w + 8a}; lane j owns key/dim cols {j, j+32}.
// All smem K/Q/P accesses vectorized as LDS.128 (KVS=68 keeps phases conflict-free).
__global__ __launch_bounds__(256) void attn_kernel(const float* __restrict__ Q,
                                                   const float* __restrict__ K,
                                                   const float* __restrict__ V) {
    __shared__ float Qs[USEL * DIM];     // 10.0 KB (pre-scaled Q)
    __shared__ float KV[64 * KVS];       // 17.0 KB (K tile, then V tile)
    __shared__ float Pt[USEL * 64];      // 10.0 KB (scores -> probs)
    __shared__ float s_m[USEL], s_l[USEL], s_f[USEL], s_tm[USEL];

    int ch = blockIdx.x, bh = blockIdx.y;
    int t = threadIdx.x;
    int i = t >> 5, j = t & 31;

    const float* Kb = K + (size_t)bh * LSEQ * DIM;
    const float* Vb = V + (size_t)bh * LSEQ * DIM;

    for (int e = t; e < USEL * DIM; e += 256) {
        int q = e >> 6, d = e & 63;
        int qi = g_topk[bh * USEL + q];
        Qs[e] = Q[((size_t)bh * LSEQ + qi) * DIM + d] * 0.125f;
    }
    if (t < USEL) { s_m[t] = -1e30f; s_l[t] = 0.f; }
    float acc[5][2];
#pragma unroll
    for (int a = 0; a < 5; a++) { acc[a][0] = 0.f; acc[a][1] = 0.f; }
    __syncthreads();

    int kbase0 = ch * CHK;
    for (int kt = 0; kt < CHK / 64; kt++) {
        int kb = kbase0 + kt * 64;

        // --- stage K tile: 1024 float4s, vectorized ---
#pragma unroll
        for (int rr = 0; rr < 4; rr++) {
            int f = t + rr * 256;
            int r = f >> 4, c4 = f & 15;
            float4 v = __ldg((const float4*)(Kb + (size_t)(kb + r) * DIM) + c4);
            *(float4*)&KV[r * KVS + c4 * 4] = v;
        }
        __syncthreads();

        // --- S = Qs @ K^T ---
        float s[5][2];
#pragma unroll
        for (int a = 0; a < 5; a++) { s[a][0] = 0.f; s[a][1] = 0.f; }
#pragma unroll
        for (int d4 = 0; d4 < 16; d4++) {
            float4 k0 = *(const float4*)&KV[j * KVS + d4 * 4];
            float4 k1 = *(const float4*)&KV[(j + 32) * KVS + d4 * 4];
#pragma unroll
            for (int a = 0; a < 5; a++) {
                float4 qv = *(const float4*)&Qs[(i + 8 * a) * 64 + d4 * 4];
                float t0 = s[a][0];
                t0 = fmaf(qv.x, k0.x, t0);
                t0 = fmaf(qv.y, k0.y, t0);
                t0 = fmaf(qv.z, k0.z, t0);
                t0 = fmaf(qv.w, k0.w, t0);
                s[a][0] = t0;
                float t1 = s[a][1];
                t1 = fmaf(qv.x, k1.x, t1);
                t1 = fmaf(qv.y, k1.y, t1);
                t1 = fmaf(qv.z, k1.z, t1);
                t1 = fmaf(qv.w, k1.w, t1);
                s[a][1] = t1;
            }
        }
#pragma unroll
        for (int a = 0; a < 5; a++) {
            Pt[(i + 8 * a) * 64 + j]      = s[a][0];
            Pt[(i + 8 * a) * 64 + j + 32] = s[a][1];
        }
        __syncthreads();

        // tile max + rescale factor; stage V over K buffer in parallel
        if (t < USEL) {
            float tm = -1e30f;
            for (int k = 0; k < 64; k++) tm = fmaxf(tm, Pt[t * 64 + k]);
            float mo = s_m[t];
            float mn = fmaxf(mo, tm);
            s_tm[t] = mn;
            s_f[t]  = __expf(mo - mn);
            s_m[t]  = mn;
        }
        __syncthreads();   // Pt max read done before exp overwrite; V staged next

#pragma unroll
        for (int rr = 0; rr < 4; rr++) {
            int f = t + rr * 256;
            int r = f >> 4, c4 = f & 15;
            float4 v = __ldg((const float4*)(Vb + (size_t)(kb + r) * DIM) + c4);
            *(float4*)&KV[r * KVS + c4 * 4] = v;
        }

        // exponentiate scores; rescale accumulators
        for (int e = t; e < USEL * 64; e += 256) {
            int q = e >> 6;
            Pt[e] = __expf(Pt[e] - s_tm[q]);
        }
#pragma unroll
        for (int a = 0; a < 5; a++) {
            float f = s_f[i + 8 * a];
            acc[a][0] *= f;
            acc[a][1] *= f;
        }
        __syncthreads();

        if (t < USEL) {
            float su = 0.f;
            for (int k = 0; k < 64; k++) su += Pt[t * 64 + k];
            s_l[t] = s_l[t] * s_f[t] + su;
        }

        // --- acc += P @ V ---
#pragma unroll
        for (int k4 = 0; k4 < 16; k4++) {
            int k = k4 * 4;
            float v00 = KV[(k + 0) * KVS + j];
            float v01 = KV[(k + 1) * KVS + j];
            float v02 = KV[(k + 2) * KVS + j];
            float v03 = KV[(k + 3) * KVS + j];
            float v10 = KV[(k + 0) * KVS + j + 32];
            float v11 = KV[(k + 1) * KVS + j + 32];
            float v12 = KV[(k + 2) * KVS + j + 32];
            float v13 = KV[(k + 3) * KVS + j + 32];
#pragma unroll
            for (int a = 0; a < 5; a++) {
                float4 p = *(const float4*)&Pt[(i + 8 * a) * 64 + k];
                float t0 = acc[a][0];
                t0 = fmaf(p.x, v00, t0);
                t0 = fmaf(p.y, v01, t0);
                t0 = fmaf(p.z, v02, t0);
                t0 = fmaf(p.w, v03, t0);
                acc[a][0] = t0;
                float t1 = acc[a][1];
                t1 = fmaf(p.x, v10, t1);
                t1 = fmaf(p.y, v11, t1);
                t1 = fmaf(p.z, v12, t1);
                t1 = fmaf(p.w, v13, t1);
                acc[a][1] = t1;
            }
        }
        __syncthreads();
    }

    float* pa = g_pacc + (size_t)(bh * NCH + ch) * USEL * DIM;
#pragma unroll
    for (int a = 0; a < 5; a++) {
        int q = i + 8 * a;
        pa[q * DIM + j]      = acc[a][0];
        pa[q * DIM + j + 32] = acc[a][1];
    }
    if (t < USEL) {
        g_pm[(bh * NCH + ch) * USEL + t] = s_m[t];
        g_pl[(bh * NCH + ch) * USEL + t] = s_l[t];
    }
}

// ================= 6. merge partials, scatter into output =================
__global__ void merge_kernel(float* __restrict__ out) {
    int u = blockIdx.x, bh = blockIdx.y, d = threadIdx.x;
    float M = -1e30f;
#pragma unroll
    for (int c = 0; c < NCH; c++)
        M = fmaxf(M, g_pm[(bh * NCH + c) * USEL + u]);
    float L = 0.f, o = 0.f;
#pragma unroll
    for (int c = 0; c < NCH; c++) {
        float w = __expf(g_pm[(bh * NCH + c) * USEL + u] - M);
        L += g_pl[(bh * NCH + c) * USEL + u] * w;
        o = fmaf(g_pacc[((size_t)(bh * NCH + c) * USEL + u) * DIM + d], w, o);
    }
    int qi = g_topk[bh * USEL + u];
    out[((size_t)bh * LSEQ + qi) * DIM + d] = o / L;
}

// ================= launcher =================
extern "C" void kernel_launch(void* const* d_in, const int* in_sizes, int n_in,
                              void* d_out, int out_size) {
    const float* Q    = (const float*)d_in[0];
    const float* K    = (const float*)d_in[1];
    const float* V    = (const float*)d_in[2];
    const int*   idxs = (const int*)d_in[3];
    float* out = (float*)d_out;
    int u = in_sizes[3] / LSEQ;   // 40

    mean_kernel<<<BH, 256>>>(V);
    fill_kernel<<<(BH * LSEQ * 16) / 256, 256>>>((float4*)out);
    m_kernel<<<BH * LSEQ / 8, 256>>>(Q, K, idxs, u);
    topk_kernel<<<BH, 256>>>();
    attn_kernel<<<dim3(NCH, BH), 256>>>(Q, K, V);
    merge_kernel<<<dim3(USEL, BH), 64>>>(out);
}